// round 2
// baseline (speedup 1.0000x reference)
#include <cuda_runtime.h>
#include <cuda_bf16.h>

#define NROWS 65536
#define BDIM  4096
#define HH    512
#define INF   64
#define DDIM  256

// ---------------- scratch (static __device__ — no allocation APIs) ----------
__device__ float g_traj_emb[BDIM * HH];                  // 8 MB
__device__ float g_emb[(size_t)NROWS * HH];              // 128 MB
__device__ float g_gi[(size_t)NROWS * 3 * HH];           // 384 MB
__device__ float g_gh[(size_t)NROWS * 3 * HH];           // 384 MB
__device__ int   g_sid[NROWS];

// ---------------- f32x2 helpers (Blackwell packed fp32) ---------------------
__device__ __forceinline__ unsigned long long dup2(float x) {
    unsigned long long r;
    asm("mov.b64 %0, {%1, %1};" : "=l"(r) : "f"(x));
    return r;
}
__device__ __forceinline__ void fma2(unsigned long long &c, unsigned long long a,
                                     unsigned long long b) {
    asm("fma.rn.f32x2 %0, %1, %2, %0;" : "+l"(c) : "l"(a), "l"(b));
}
__device__ __forceinline__ float2 unpk(unsigned long long v) {
    float2 r;
    asm("mov.b64 {%0, %1}, %2;" : "=f"(r.x), "=f"(r.y) : "l"(v));
    return r;
}

// ---------------- sample-id (searchsorted right - 1) ------------------------
__global__ void sid_kernel(const int* __restrict__ starts, int* __restrict__ sid) {
    int i = blockIdx.x * 256 + threadIdx.x;
    if (i >= NROWS) return;
    int lo = 0, hi = BDIM - 1;  // largest s with starts[s] <= i  (starts[0]==0)
    while (lo < hi) {
        int mid = (lo + hi + 1) >> 1;
        if (starts[mid] <= i) lo = mid; else hi = mid - 1;
    }
    sid[i] = lo;
}

// ---------------- GEMM: 128x128x16, double-buffered, FFMA2 micro-kernel -----
// MODE 0: C[M,512] = A[M,512] @ B[512,512]          (B row-major, j contiguous)
// MODE 1: C[N,512] = relu( concat(neigh,dist) @ Wsel + traj_emb[sid] + bias )
//         A=neighbor_t (K 0..63), A2=dist (K 64..319); B rows remapped
//         (gk<64 -> W row gk, else W row gk+512)
// MODE 2: C[M,1536 tile] = A[M,512] @ B^T,  B = [1536,512] K-contiguous
#define TK  16
#define PADL 132

template<int MODE>
__global__ __launch_bounds__(256)
void gemm_kernel(const float* __restrict__ A, const float* __restrict__ A2,
                 const float* __restrict__ B, float* __restrict__ C,
                 int lda, int ldb, int ldc, int K,
                 const float* __restrict__ addv, const float* __restrict__ bias,
                 const int* __restrict__ sid)
{
    __shared__ float As[2][TK][PADL];
    __shared__ float Bs[2][TK][PADL];

    const int tid = threadIdx.x;
    const int tx  = tid & 15, ty = tid >> 4;
    const int tx4 = tx * 4,  ty4 = ty * 4;
    const int m0 = blockIdx.y * 128;
    const int n0 = blockIdx.x * 128;

    int rowA[2], kvA[2], krB[2], jvB[2];
#pragma unroll
    for (int i = 0; i < 2; i++) {
        int l = i * 256 + tid;
        rowA[i] = l >> 2;  kvA[i] = (l & 3) * 4;   // [row 0..127][kvec*4]
        krB[i]  = l >> 5;  jvB[i] = (l & 31) * 4;  // [k 0..15][jvec*4]
    }

    unsigned long long acc[4][8];
#pragma unroll
    for (int i = 0; i < 4; i++)
#pragma unroll
        for (int j = 0; j < 8; j++) acc[i][j] = 0ull;

    const int tiles = K / TK;

    auto fetchA = [&](int kt, float4* ra) {
#pragma unroll
        for (int i = 0; i < 2; i++) {
            int gk = kt * TK + kvA[i];
            int r  = m0 + rowA[i];
            if (MODE == 1) {
                if (gk < INF) ra[i] = *(const float4*)(A  + (size_t)r * INF  + gk);
                else          ra[i] = *(const float4*)(A2 + (size_t)r * DDIM + (gk - INF));
            } else {
                ra[i] = *(const float4*)(A + (size_t)r * lda + gk);
            }
        }
    };
    auto fetchB = [&](int kt, float4* rb) {
#pragma unroll
        for (int i = 0; i < 2; i++) {
            if (MODE == 2) {
                int gk = kt * TK + kvA[i];
                int j  = n0 + rowA[i];
                rb[i] = *(const float4*)(B + (size_t)j * ldb + gk);
            } else {
                int gk = kt * TK + krB[i];
                int wr = (MODE == 1) ? (gk < INF ? gk : gk + 512) : gk;
                rb[i] = *(const float4*)(B + (size_t)wr * ldb + n0 + jvB[i]);
            }
        }
    };
    auto stA = [&](int nb, const float4* ra) {
#pragma unroll
        for (int i = 0; i < 2; i++) {
            As[nb][kvA[i] + 0][rowA[i]] = ra[i].x;
            As[nb][kvA[i] + 1][rowA[i]] = ra[i].y;
            As[nb][kvA[i] + 2][rowA[i]] = ra[i].z;
            As[nb][kvA[i] + 3][rowA[i]] = ra[i].w;
        }
    };
    auto stB = [&](int nb, const float4* rb) {
#pragma unroll
        for (int i = 0; i < 2; i++) {
            if (MODE == 2) {
                Bs[nb][kvA[i] + 0][rowA[i]] = rb[i].x;
                Bs[nb][kvA[i] + 1][rowA[i]] = rb[i].y;
                Bs[nb][kvA[i] + 2][rowA[i]] = rb[i].z;
                Bs[nb][kvA[i] + 3][rowA[i]] = rb[i].w;
            } else {
                *(float4*)&Bs[nb][krB[i]][jvB[i]] = rb[i];
            }
        }
    };

    {
        float4 ra[2], rb[2];
        fetchA(0, ra); fetchB(0, rb);
        stA(0, ra);    stB(0, rb);
    }
    __syncthreads();

    int buf = 0;
    for (int kt = 0; kt < tiles; kt++) {
        float4 ra[2], rb[2];
        const bool more = (kt + 1 < tiles);
        if (more) { fetchA(kt + 1, ra); fetchB(kt + 1, rb); }

#pragma unroll
        for (int k = 0; k < TK; k++) {
            ulonglong2 au0 = *(const ulonglong2*)&As[buf][k][ty4];
            ulonglong2 au1 = *(const ulonglong2*)&As[buf][k][64 + ty4];
            float4 bf0 = *(const float4*)&Bs[buf][k][tx4];
            float4 bf1 = *(const float4*)&Bs[buf][k][64 + tx4];
            unsigned long long a2[4] = {au0.x, au0.y, au1.x, au1.y};
            unsigned long long bb[8] = {dup2(bf0.x), dup2(bf0.y), dup2(bf0.z), dup2(bf0.w),
                                        dup2(bf1.x), dup2(bf1.y), dup2(bf1.z), dup2(bf1.w)};
#pragma unroll
            for (int mp = 0; mp < 4; mp++)
#pragma unroll
                for (int c = 0; c < 8; c++)
                    fma2(acc[mp][c], a2[mp], bb[c]);
        }

        if (more) { stA(buf ^ 1, ra); stB(buf ^ 1, rb); }
        __syncthreads();
        buf ^= 1;
    }

    // ---------------- epilogue: coalesced float4 stores ----------------
    float2 u[4][8];
#pragma unroll
    for (int mp = 0; mp < 4; mp++)
#pragma unroll
        for (int c = 0; c < 8; c++) u[mp][c] = unpk(acc[mp][c]);

#pragma unroll
    for (int g = 0; g < 2; g++) {
#pragma unroll
        for (int pr = 0; pr < 2; pr++) {
            const int mp = g * 2 + pr;
#pragma unroll
            for (int lane = 0; lane < 2; lane++) {
                const int r = m0 + g * 64 + ty4 + pr * 2 + lane;
#pragma unroll
                for (int cg = 0; cg < 2; cg++) {
                    const int col = n0 + cg * 64 + tx4;
                    float4 v;
                    v.x = lane ? u[mp][cg * 4 + 0].y : u[mp][cg * 4 + 0].x;
                    v.y = lane ? u[mp][cg * 4 + 1].y : u[mp][cg * 4 + 1].x;
                    v.z = lane ? u[mp][cg * 4 + 2].y : u[mp][cg * 4 + 2].x;
                    v.w = lane ? u[mp][cg * 4 + 3].y : u[mp][cg * 4 + 3].x;
                    if (MODE == 1) {
                        const int s = sid[r];
                        float4 tv = *(const float4*)&addv[(size_t)s * HH + col];
                        float4 bv = *(const float4*)&bias[col];
                        v.x = fmaxf(v.x + tv.x + bv.x, 0.f);
                        v.y = fmaxf(v.y + tv.y + bv.y, 0.f);
                        v.z = fmaxf(v.z + tv.z + bv.z, 0.f);
                        v.w = fmaxf(v.w + tv.w + bv.w, 0.f);
                    }
                    *(float4*)&C[(size_t)r * ldc + col] = v;
                }
            }
        }
    }
}

// ---------------- GRU gates (elementwise, vec4) -----------------------------
__device__ __forceinline__ float sigf(float x) { return 1.f / (1.f + __expf(-x)); }
__device__ __forceinline__ float tanhfast(float x) {
    float ax = fabsf(x);
    float e  = __expf(-2.f * ax);
    float t  = (1.f - e) / (1.f + e);
    return copysignf(t, x);
}
__device__ __forceinline__ float gru1(float sr, float sz, float i_n, float h_n, float h) {
    float r = sigf(sr);
    float z = sigf(sz);
    float n = tanhfast(i_n + r * h_n);
    return (1.f - z) * n + z * h;
}

__global__ __launch_bounds__(256)
void gates_kernel(const float* __restrict__ gi, const float* __restrict__ gh,
                  const float* __restrict__ ht,
                  const float* __restrict__ b_ih, const float* __restrict__ b_hh,
                  float* __restrict__ out)
{
    int idx = blockIdx.x * 256 + threadIdx.x;   // N*128 vec4 slots
    int row = idx >> 7;
    int c4  = (idx & 127) * 4;
    size_t gb = (size_t)row * 1536 + c4;

    float4 ir  = *(const float4*)(gi + gb);
    float4 iz  = *(const float4*)(gi + gb + 512);
    float4 inn = *(const float4*)(gi + gb + 1024);
    float4 hr  = *(const float4*)(gh + gb);
    float4 hz  = *(const float4*)(gh + gb + 512);
    float4 hnn = *(const float4*)(gh + gb + 1024);
    float4 bir = *(const float4*)(b_ih + c4);
    float4 biz = *(const float4*)(b_ih + 512 + c4);
    float4 bin = *(const float4*)(b_ih + 1024 + c4);
    float4 bhr = *(const float4*)(b_hh + c4);
    float4 bhz = *(const float4*)(b_hh + 512 + c4);
    float4 bhn = *(const float4*)(b_hh + 1024 + c4);
    float4 h   = *(const float4*)(ht + (size_t)row * HH + c4);

    float4 o;
    o.x = gru1(ir.x + bir.x + hr.x + bhr.x, iz.x + biz.x + hz.x + bhz.x,
               inn.x + bin.x, hnn.x + bhn.x, h.x);
    o.y = gru1(ir.y + bir.y + hr.y + bhr.y, iz.y + biz.y + hz.y + bhz.y,
               inn.y + bin.y, hnn.y + bhn.y, h.y);
    o.z = gru1(ir.z + bir.z + hr.z + bhr.z, iz.z + biz.z + hz.z + bhz.z,
               inn.z + bin.z, hnn.z + bhn.z, h.z);
    o.w = gru1(ir.w + bir.w + hr.w + bhr.w, iz.w + biz.w + hz.w + bhz.w,
               inn.w + bin.w, hnn.w + bhn.w, h.w);
    *(float4*)(out + (size_t)row * HH + c4) = o;
}

// ---------------- launch ----------------------------------------------------
extern "C" void kernel_launch(void* const* d_in, const int* in_sizes, int n_in,
                              void* d_out, int out_size)
{
    const float* traj  = (const float*)d_in[0];   // [4096, 512]
    const float* neigh = (const float*)d_in[1];   // [65536, 64]
    const float* dist  = (const float*)d_in[2];   // [65536, 256]
    const float* ht    = (const float*)d_in[3];   // [65536, 512]
    const float* W_emb = (const float*)d_in[4];   // [832, 512]
    const float* b_emb = (const float*)d_in[5];   // [512]
    const float* w_ih  = (const float*)d_in[6];   // [1536, 512]
    const float* w_hh  = (const float*)d_in[7];   // [1536, 512]
    const float* b_ih  = (const float*)d_in[8];   // [1536]
    const float* b_hh  = (const float*)d_in[9];   // [1536]
    const int*   starts = (const int*)d_in[10];   // [4096]
    float* out = (float*)d_out;                   // [65536, 512]

    float *p_traj_emb, *p_emb, *p_gi, *p_gh;
    int* p_sid;
    cudaGetSymbolAddress((void**)&p_traj_emb, g_traj_emb);
    cudaGetSymbolAddress((void**)&p_emb, g_emb);
    cudaGetSymbolAddress((void**)&p_gi, g_gi);
    cudaGetSymbolAddress((void**)&p_gh, g_gh);
    cudaGetSymbolAddress((void**)&p_sid, g_sid);

    // 1) sample id per flat neighbor row
    sid_kernel<<<NROWS / 256, 256>>>(starts, p_sid);

    // 2) traj_emb = traj_input @ W_emb[64:576, :]   (per-sample, tiny)
    gemm_kernel<0><<<dim3(HH / 128, BDIM / 128), 256>>>(
        traj, nullptr, W_emb + (size_t)INF * HH, p_traj_emb,
        HH, HH, HH, HH, nullptr, nullptr, nullptr);

    // 3) emb = relu(neigh@W[0:64] + dist@W[576:832] + traj_emb[sid] + b_emb)
    gemm_kernel<1><<<dim3(HH / 128, NROWS / 128), 256>>>(
        neigh, dist, W_emb, p_emb,
        0, HH, HH, INF + DDIM, p_traj_emb, b_emb, p_sid);

    // 4) gi = emb @ w_ih^T ;  gh = ht @ w_hh^T
    gemm_kernel<2><<<dim3(1536 / 128, NROWS / 128), 256>>>(
        p_emb, nullptr, w_ih, p_gi,
        HH, HH, 1536, HH, nullptr, nullptr, nullptr);
    gemm_kernel<2><<<dim3(1536 / 128, NROWS / 128), 256>>>(
        ht, nullptr, w_hh, p_gh,
        HH, HH, 1536, HH, nullptr, nullptr, nullptr);

    // 5) GRU gates -> out
    gates_kernel<<<(NROWS * 128) / 256, 256>>>(p_gi, p_gh, ht, b_ih, b_hh, out);
}

// round 5
// speedup vs baseline: 3.6766x; 3.6766x over previous
#include <cuda_runtime.h>
#include <cuda_fp16.h>
#include <cstdint>

#define NROWS 65536
#define BDIM  4096
#define HH    512
#define INF   64
#define DDIM  256

// ---------------- scratch (static __device__ — no allocation APIs) ----------
__device__ float  g_traj_emb[BDIM * HH];                 // 8 MB  (f32)
__device__ __half g_emb_h[(size_t)NROWS * HH];           // 64 MB (f16)
__device__ __half g_ht_h[(size_t)NROWS * HH];            // 64 MB (f16)
__device__ __half g_wih_h[(size_t)3 * HH * HH];          // 1.5 MB
__device__ __half g_whh_h[(size_t)3 * HH * HH];          // 1.5 MB
__device__ int    g_sid[NROWS];

// ---------------- f32x2 helpers (Blackwell packed fp32) ---------------------
__device__ __forceinline__ unsigned long long dup2(float x) {
    unsigned long long r;
    asm("mov.b64 %0, {%1, %1};" : "=l"(r) : "f"(x));
    return r;
}
__device__ __forceinline__ void fma2(unsigned long long &c, unsigned long long a,
                                     unsigned long long b) {
    asm("fma.rn.f32x2 %0, %1, %2, %0;" : "+l"(c) : "l"(a), "l"(b));
}
__device__ __forceinline__ float2 unpk(unsigned long long v) {
    float2 r;
    asm("mov.b64 {%0, %1}, %2;" : "=f"(r.x), "=f"(r.y) : "l"(v));
    return r;
}

__device__ __forceinline__ uint32_t smem_u32(const void* p) {
    uint32_t a;
    asm("{ .reg .u64 t; cvta.to.shared.u64 t, %1; cvt.u32.u64 %0, t; }" : "=r"(a) : "l"(p));
    return a;
}
#define SWZ128(o) ((o) ^ (((o) >> 3) & 0x70))

// ---------------- sample-id (searchsorted right - 1) ------------------------
__global__ void sid_kernel(const int* __restrict__ starts, int* __restrict__ sid) {
    int i = blockIdx.x * 256 + threadIdx.x;
    if (i >= NROWS) return;
    int lo = 0, hi = BDIM - 1;
    while (lo < hi) {
        int mid = (lo + hi + 1) >> 1;
        if (starts[mid] <= i) lo = mid; else hi = mid - 1;
    }
    sid[i] = lo;
}

// ---------------- f32 -> f16 convert ----------------------------------------
__global__ __launch_bounds__(256)
void cvt_kernel(const float* __restrict__ src, __half* __restrict__ dst, int n4) {
    int i = blockIdx.x * 256 + threadIdx.x;
    if (i >= n4) return;
    float4 v = ((const float4*)src)[i];
    ((__half2*)dst)[2 * i]     = __floats2half2_rn(v.x, v.y);
    ((__half2*)dst)[2 * i + 1] = __floats2half2_rn(v.z, v.w);
}

// ---------------- FFMA2 GEMM (modes 0 and 1) --------------------------------
// MODE 0: C(f32)[M,512] = A[M,512] @ B[512,512]
// MODE 1: C(f16)[N,512] = relu( concat(neigh,dist)@Wsel + traj_emb[sid] + bias )
#define TK  16
#define PADL 132

template<int MODE>
__global__ __launch_bounds__(256)
void gemm_kernel(const float* __restrict__ A, const float* __restrict__ A2,
                 const float* __restrict__ B, void* __restrict__ Cv,
                 int lda, int ldb, int ldc, int K,
                 const float* __restrict__ addv, const float* __restrict__ bias,
                 const int* __restrict__ sid)
{
    __shared__ float As[2][TK][PADL];
    __shared__ float Bs[2][TK][PADL];

    float*  Cf = (float*)Cv;
    __half* Ch = (__half*)Cv;

    const int tid = threadIdx.x;
    const int tx  = tid & 15, ty = tid >> 4;
    const int tx4 = tx * 4,  ty4 = ty * 4;
    const int m0 = blockIdx.y * 128;
    const int n0 = blockIdx.x * 128;

    int rowA[2], kvA[2], krB[2], jvB[2];
#pragma unroll
    for (int i = 0; i < 2; i++) {
        int l = i * 256 + tid;
        rowA[i] = l >> 2;  kvA[i] = (l & 3) * 4;
        krB[i]  = l >> 5;  jvB[i] = (l & 31) * 4;
    }

    unsigned long long acc[4][8];
#pragma unroll
    for (int i = 0; i < 4; i++)
#pragma unroll
        for (int j = 0; j < 8; j++) acc[i][j] = 0ull;

    const int tiles = K / TK;

    auto fetchA = [&](int kt, float4* ra) {
#pragma unroll
        for (int i = 0; i < 2; i++) {
            int gk = kt * TK + kvA[i];
            int r  = m0 + rowA[i];
            if (MODE == 1) {
                if (gk < INF) ra[i] = *(const float4*)(A  + (size_t)r * INF  + gk);
                else          ra[i] = *(const float4*)(A2 + (size_t)r * DDIM + (gk - INF));
            } else {
                ra[i] = *(const float4*)(A + (size_t)r * lda + gk);
            }
        }
    };
    auto fetchB = [&](int kt, float4* rb) {
#pragma unroll
        for (int i = 0; i < 2; i++) {
            int gk = kt * TK + krB[i];
            int wr = (MODE == 1) ? (gk < INF ? gk : gk + 512) : gk;
            rb[i] = *(const float4*)(B + (size_t)wr * ldb + n0 + jvB[i]);
        }
    };
    auto stA = [&](int nb, const float4* ra) {
#pragma unroll
        for (int i = 0; i < 2; i++) {
            As[nb][kvA[i] + 0][rowA[i]] = ra[i].x;
            As[nb][kvA[i] + 1][rowA[i]] = ra[i].y;
            As[nb][kvA[i] + 2][rowA[i]] = ra[i].z;
            As[nb][kvA[i] + 3][rowA[i]] = ra[i].w;
        }
    };
    auto stB = [&](int nb, const float4* rb) {
#pragma unroll
        for (int i = 0; i < 2; i++)
            *(float4*)&Bs[nb][krB[i]][jvB[i]] = rb[i];
    };

    {
        float4 ra[2], rb[2];
        fetchA(0, ra); fetchB(0, rb);
        stA(0, ra);    stB(0, rb);
    }
    __syncthreads();

    int buf = 0;
    for (int kt = 0; kt < tiles; kt++) {
        float4 ra[2], rb[2];
        const bool more = (kt + 1 < tiles);
        if (more) { fetchA(kt + 1, ra); fetchB(kt + 1, rb); }

#pragma unroll
        for (int k = 0; k < TK; k++) {
            ulonglong2 au0 = *(const ulonglong2*)&As[buf][k][ty4];
            ulonglong2 au1 = *(const ulonglong2*)&As[buf][k][64 + ty4];
            float4 bf0 = *(const float4*)&Bs[buf][k][tx4];
            float4 bf1 = *(const float4*)&Bs[buf][k][64 + tx4];
            unsigned long long a2[4] = {au0.x, au0.y, au1.x, au1.y};
            unsigned long long bb[8] = {dup2(bf0.x), dup2(bf0.y), dup2(bf0.z), dup2(bf0.w),
                                        dup2(bf1.x), dup2(bf1.y), dup2(bf1.z), dup2(bf1.w)};
#pragma unroll
            for (int mp = 0; mp < 4; mp++)
#pragma unroll
                for (int c = 0; c < 8; c++)
                    fma2(acc[mp][c], a2[mp], bb[c]);
        }

        if (more) { stA(buf ^ 1, ra); stB(buf ^ 1, rb); }
        __syncthreads();
        buf ^= 1;
    }

    float2 u[4][8];
#pragma unroll
    for (int mp = 0; mp < 4; mp++)
#pragma unroll
        for (int c = 0; c < 8; c++) u[mp][c] = unpk(acc[mp][c]);

#pragma unroll
    for (int g = 0; g < 2; g++) {
#pragma unroll
        for (int pr = 0; pr < 2; pr++) {
            const int mp = g * 2 + pr;
#pragma unroll
            for (int lane = 0; lane < 2; lane++) {
                const int r = m0 + g * 64 + ty4 + pr * 2 + lane;
#pragma unroll
                for (int cg = 0; cg < 2; cg++) {
                    const int col = n0 + cg * 64 + tx4;
                    float4 v;
                    v.x = lane ? u[mp][cg * 4 + 0].y : u[mp][cg * 4 + 0].x;
                    v.y = lane ? u[mp][cg * 4 + 1].y : u[mp][cg * 4 + 1].x;
                    v.z = lane ? u[mp][cg * 4 + 2].y : u[mp][cg * 4 + 2].x;
                    v.w = lane ? u[mp][cg * 4 + 3].y : u[mp][cg * 4 + 3].x;
                    if (MODE == 1) {
                        const int s = sid[r];
                        float4 tv = *(const float4*)&addv[(size_t)s * HH + col];
                        float4 bv = *(const float4*)&bias[col];
                        v.x = fmaxf(v.x + tv.x + bv.x, 0.f);
                        v.y = fmaxf(v.y + tv.y + bv.y, 0.f);
                        v.z = fmaxf(v.z + tv.z + bv.z, 0.f);
                        v.w = fmaxf(v.w + tv.w + bv.w, 0.f);
                        __half2* d = (__half2*)(Ch + (size_t)r * ldc + col);
                        d[0] = __floats2half2_rn(v.x, v.y);
                        d[1] = __floats2half2_rn(v.z, v.w);
                    } else {
                        *(float4*)&Cf[(size_t)r * ldc + col] = v;
                    }
                }
            }
        }
    }
}

// ---------------- GRU gate math ---------------------------------------------
__device__ __forceinline__ float sigf(float x) { return 1.f / (1.f + __expf(-x)); }
__device__ __forceinline__ float tanhfast(float x) {
    float ax = fabsf(x);
    float e  = __expf(-2.f * ax);
    float t  = (1.f - e) / (1.f + e);
    return copysignf(t, x);
}
__device__ __forceinline__ float gru1(float sr, float sz, float i_n, float h_n, float h) {
    float r = sigf(sr);
    float z = sigf(sz);
    float n = tanhfast(i_n + r * h_n);
    return (1.f - z) * n + z * h;
}

// ---------------- fused HMMA kernel: gi/gh GEMMs + gates --------------------
// CTA tile: 128 rows x 64 gate-cols. 8 warps; warp = 16 rows x 64 cols.
// 4 f32 accumulator groups per thread (m16n8k16 fragments):
//   0: r-gate  (emb@w_ih_r^T + ht@w_hh_r^T, K=1024)
//   1: z-gate  (K=1024)
//   2: i_n = emb@w_ih_n^T (K=512)    3: h_n = ht@w_hh_n^T (K=512)
// SMEM stage (40KB): A 128x64 f16 (16KB) + 3 B gate tiles 64x64 f16 (8KB each).
#define FG_STAGE 40960u
#define FG_BIAS  81920u
#define FG_SMEM  83200u

__device__ __forceinline__ void ldsm4(uint32_t &r0, uint32_t &r1, uint32_t &r2,
                                      uint32_t &r3, uint32_t addr) {
    asm volatile("ldmatrix.sync.aligned.m8n8.x4.shared.b16 {%0,%1,%2,%3}, [%4];"
                 : "=r"(r0), "=r"(r1), "=r"(r2), "=r"(r3) : "r"(addr));
}
__device__ __forceinline__ void hmma(float (&d)[4], uint32_t a0, uint32_t a1,
                                     uint32_t a2, uint32_t a3, uint32_t b0, uint32_t b1) {
    asm volatile("mma.sync.aligned.m16n8k16.row.col.f32.f16.f16.f32 "
                 "{%0,%1,%2,%3}, {%4,%5,%6,%7}, {%8,%9}, {%0,%1,%2,%3};"
                 : "+f"(d[0]), "+f"(d[1]), "+f"(d[2]), "+f"(d[3])
                 : "r"(a0), "r"(a1), "r"(a2), "r"(a3), "r"(b0), "r"(b1));
}

template<int PHASE>
__device__ __forceinline__ void gemm_phase(
    uint32_t sb, const __half* __restrict__ Asrc, const __half* __restrict__ Bsrc,
    int m0, int j0, int tid, int wid, int lane, float (&acc)[4][8][4])
{
    uint4 pf[10];

    auto fetch = [&](int kc) {
#pragma unroll
        for (int i = 0; i < 10; i++) {
            int u = i * 256 + tid;
            const __half* src;
            if (u < 1024) {
                src = Asrc + (size_t)(m0 + (u >> 3)) * 512 + kc * 64 + (u & 7) * 8;
            } else {
                int v = u - 1024, g = v >> 9, w = v & 511;
                src = Bsrc + (size_t)(g * 512 + j0 + (w >> 3)) * 512 + kc * 64 + (w & 7) * 8;
            }
            pf[i] = *(const uint4*)src;
        }
    };
    auto store = [&](int buf) {
        const uint32_t bb = sb + (uint32_t)buf * FG_STAGE;
#pragma unroll
        for (int i = 0; i < 10; i++) {
            int u = i * 256 + tid;
            uint32_t off;
            if (u < 1024) {
                off = SWZ128((uint32_t)((u >> 3) * 128 + (u & 7) * 16));
            } else {
                int v = u - 1024, g = v >> 9, w = v & 511;
                off = 16384u + (uint32_t)g * 8192u +
                      SWZ128((uint32_t)((w >> 3) * 128 + (w & 7) * 16));
            }
            asm volatile("st.shared.v4.b32 [%0], {%1,%2,%3,%4};"
                         :: "r"(bb + off), "r"(pf[i].x), "r"(pf[i].y),
                            "r"(pf[i].z), "r"(pf[i].w));
        }
    };

    const uint32_t arow = (uint32_t)((wid << 4) + (lane & 15)) * 128u + ((lane >> 4) << 4);
    const int brow = (lane & 7) + ((lane >> 4) << 3);
    const uint32_t bkoff = (uint32_t)(((lane >> 3) & 1) << 4);

    fetch(0); store(0); __syncthreads();

    for (int kc = 0; kc < 8; kc++) {
        const int cur = kc & 1;
        if (kc < 7) fetch(kc + 1);

        const uint32_t base = sb + (uint32_t)cur * FG_STAGE;
#pragma unroll
        for (int ks = 0; ks < 4; ks++) {
            uint32_t a0, a1, a2, a3;
            ldsm4(a0, a1, a2, a3, base + SWZ128(arow + (uint32_t)ks * 32u));
#pragma unroll
            for (int g = 0; g < 3; g++) {
                const int grp = (g < 2) ? g : (2 + PHASE);
                const uint32_t boff = 16384u + (uint32_t)g * 8192u;
#pragma unroll
                for (int nf2 = 0; nf2 < 4; nf2++) {
                    uint32_t b0, b1, b2, b3;
                    uint32_t ba = base + boff +
                        SWZ128((uint32_t)((nf2 * 16 + brow) * 128) +
                               (uint32_t)ks * 32u + bkoff);
                    ldsm4(b0, b1, b2, b3, ba);
                    hmma(acc[grp][nf2 * 2],     a0, a1, a2, a3, b0, b1);
                    hmma(acc[grp][nf2 * 2 + 1], a0, a1, a2, a3, b2, b3);
                }
            }
        }

        if (kc < 7) { store(cur ^ 1); __syncthreads(); }
    }
}

__global__ __launch_bounds__(256, 1)
void fused_gru_kernel(const __half* __restrict__ emb_h, const __half* __restrict__ ht_h,
                      const __half* __restrict__ wih_h, const __half* __restrict__ whh_h,
                      const float* __restrict__ ht,
                      const float* __restrict__ b_ih, const float* __restrict__ b_hh,
                      float* __restrict__ out)
{
    extern __shared__ char smem[];
    const uint32_t sb = smem_u32(smem);
    const int tid = threadIdx.x, wid = tid >> 5, lane = tid & 31;
    const int m0 = blockIdx.y * 128;
    const int j0 = blockIdx.x * 64;

    float* bp = (float*)(smem + FG_BIAS);
    if (tid < 64) {
        int j = j0 + tid;
        bp[tid]       = b_ih[j]        + b_hh[j];
        bp[64 + tid]  = b_ih[512 + j]  + b_hh[512 + j];
        bp[128 + tid] = b_ih[1024 + j];
        bp[192 + tid] = b_hh[1024 + j];
    }

    float acc[4][8][4];
#pragma unroll
    for (int g = 0; g < 4; g++)
#pragma unroll
        for (int n = 0; n < 8; n++)
#pragma unroll
            for (int e = 0; e < 4; e++) acc[g][n][e] = 0.f;

    gemm_phase<0>(sb, emb_h, wih_h, m0, j0, tid, wid, lane, acc);
    __syncthreads();                    // last buf of phase 0 fully consumed
    gemm_phase<1>(sb, ht_h, whh_h, m0, j0, tid, wid, lane, acc);

    // ---------------- GRU epilogue (all in registers + f32 ht) --------------
    const int t4 = lane & 3, gid = lane >> 2;
    const int r0 = m0 + wid * 16 + gid;

#pragma unroll
    for (int nf = 0; nf < 8; nf++) {
        const int c = nf * 8 + 2 * t4;              // col within 64-wide tile
        const float* hp0 = ht + (size_t)r0 * HH + j0 + c;
        const float* hp1 = hp0 + 8 * HH;
        float2 h0 = *(const float2*)hp0;
        float2 h1 = *(const float2*)hp1;

        float2 o0, o1;
        o0.x = gru1(acc[0][nf][0] + bp[c],     acc[1][nf][0] + bp[64 + c],
                    acc[2][nf][0] + bp[128 + c], acc[3][nf][0] + bp[192 + c], h0.x);
        o0.y = gru1(acc[0][nf][1] + bp[c + 1], acc[1][nf][1] + bp[64 + c + 1],
                    acc[2][nf][1] + bp[128 + c + 1], acc[3][nf][1] + bp[192 + c + 1], h0.y);
        o1.x = gru1(acc[0][nf][2] + bp[c],     acc[1][nf][2] + bp[64 + c],
                    acc[2][nf][2] + bp[128 + c], acc[3][nf][2] + bp[192 + c], h1.x);
        o1.y = gru1(acc[0][nf][3] + bp[c + 1], acc[1][nf][3] + bp[64 + c + 1],
                    acc[2][nf][3] + bp[128 + c + 1], acc[3][nf][3] + bp[192 + c + 1], h1.y);

        *(float2*)(out + (size_t)r0 * HH + j0 + c)       = o0;
        *(float2*)(out + (size_t)(r0 + 8) * HH + j0 + c) = o1;
    }
}

// ---------------- launch ----------------------------------------------------
extern "C" void kernel_launch(void* const* d_in, const int* in_sizes, int n_in,
                              void* d_out, int out_size)
{
    const float* traj  = (const float*)d_in[0];   // [4096, 512]
    const float* neigh = (const float*)d_in[1];   // [65536, 64]
    const float* dist  = (const float*)d_in[2];   // [65536, 256]
    const float* ht    = (const float*)d_in[3];   // [65536, 512]
    const float* W_emb = (const float*)d_in[4];   // [832, 512]
    const float* b_emb = (const float*)d_in[5];   // [512]
    const float* w_ih  = (const float*)d_in[6];   // [1536, 512]
    const float* w_hh  = (const float*)d_in[7];   // [1536, 512]
    const float* b_ih  = (const float*)d_in[8];   // [1536]
    const float* b_hh  = (const float*)d_in[9];   // [1536]
    const int*   starts = (const int*)d_in[10];   // [4096]
    float* out = (float*)d_out;                   // [65536, 512]

    float *p_traj_emb;
    __half *p_emb_h, *p_ht_h, *p_wih_h, *p_whh_h;
    int* p_sid;
    cudaGetSymbolAddress((void**)&p_traj_emb, g_traj_emb);
    cudaGetSymbolAddress((void**)&p_emb_h, g_emb_h);
    cudaGetSymbolAddress((void**)&p_ht_h, g_ht_h);
    cudaGetSymbolAddress((void**)&p_wih_h, g_wih_h);
    cudaGetSymbolAddress((void**)&p_whh_h, g_whh_h);
    cudaGetSymbolAddress((void**)&p_sid, g_sid);

    cudaFuncSetAttribute(fused_gru_kernel,
                         cudaFuncAttributeMaxDynamicSharedMemorySize, FG_SMEM);

    // 1) sample ids + f16 conversions (independent)
    sid_kernel<<<NROWS / 256, 256>>>(starts, p_sid);
    cvt_kernel<<<(NROWS * HH / 4) / 256, 256>>>(ht, p_ht_h, NROWS * HH / 4);
    cvt_kernel<<<(3 * HH * HH / 4 + 255) / 256, 256>>>(w_ih, p_wih_h, 3 * HH * HH / 4);
    cvt_kernel<<<(3 * HH * HH / 4 + 255) / 256, 256>>>(w_hh, p_whh_h, 3 * HH * HH / 4);

    // 2) traj_emb = traj_input @ W_emb[64:576, :]
    gemm_kernel<0><<<dim3(HH / 128, BDIM / 128), 256>>>(
        traj, nullptr, W_emb + (size_t)INF * HH, p_traj_emb,
        HH, HH, HH, HH, nullptr, nullptr, nullptr);

    // 3) emb(f16) = relu(neigh@W[0:64] + dist@W[576:832] + traj_emb[sid] + b_emb)
    gemm_kernel<1><<<dim3(HH / 128, NROWS / 128), 256>>>(
        neigh, dist, W_emb, p_emb_h,
        0, HH, HH, INF + DDIM, p_traj_emb, b_emb, p_sid);

    // 4) fused: gi/gh GEMMs (HMMA f16) + GRU gates -> out
    fused_gru_kernel<<<dim3(HH / 64, NROWS / 128), 256, FG_SMEM>>>(
        p_emb_h, p_ht_h, p_wih_h, p_whh_h, ht, b_ih, b_hh, out);
}

// round 7
// speedup vs baseline: 4.8075x; 1.3076x over previous
#include <cuda_runtime.h>
#include <cuda_fp16.h>
#include <cstdint>

#define NROWS 65536
#define BDIM  4096
#define HH    512
#define INF   64
#define DDIM  256
#define EK    320          // fused input K for emb GEMM (64 + 256)

// ---------------- scratch (static __device__ — no allocation APIs) ----------
__device__ float  g_traj_emb[BDIM * HH];                 // 8 MB  (f32)
__device__ __half g_x_h[(size_t)NROWS * EK];             // 40 MB (f16 packed neigh|dist)
__device__ __half g_wembT_h[(size_t)HH * EK];            // 320 KB (f16, [n][k] K-contig)
__device__ __half g_emb_h[(size_t)NROWS * HH];           // 64 MB (f16)
__device__ __half g_ht_h[(size_t)NROWS * HH];            // 64 MB (f16)
__device__ __half g_wih_h[(size_t)3 * HH * HH];          // 1.5 MB
__device__ __half g_whh_h[(size_t)3 * HH * HH];          // 1.5 MB
__device__ int    g_sid[NROWS];

// ---------------- helpers ----------------------------------------------------
__device__ __forceinline__ uint32_t h2u(__half2 h) {
    uint32_t u;
    asm("mov.b32 %0, %1;" : "=r"(u) : "r"(*reinterpret_cast<uint32_t*>(&h)));
    return u;
}

// ---------------- f32x2 helpers (Blackwell packed fp32) ---------------------
__device__ __forceinline__ unsigned long long dup2(float x) {
    unsigned long long r;
    asm("mov.b64 %0, {%1, %1};" : "=l"(r) : "f"(x));
    return r;
}
__device__ __forceinline__ void fma2(unsigned long long &c, unsigned long long a,
                                     unsigned long long b) {
    asm("fma.rn.f32x2 %0, %1, %2, %0;" : "+l"(c) : "l"(a), "l"(b));
}
__device__ __forceinline__ float2 unpk(unsigned long long v) {
    float2 r;
    asm("mov.b64 {%0, %1}, %2;" : "=f"(r.x), "=f"(r.y) : "l"(v));
    return r;
}

__device__ __forceinline__ uint32_t smem_u32(const void* p) {
    uint32_t a;
    asm("{ .reg .u64 t; cvta.to.shared.u64 t, %1; cvt.u32.u64 %0, t; }" : "=r"(a) : "l"(p));
    return a;
}
#define SWZ128(o) ((o) ^ (((o) >> 3) & 0x70))

// ---------------- HMMA primitives -------------------------------------------
__device__ __forceinline__ void ldsm4(uint32_t &r0, uint32_t &r1, uint32_t &r2,
                                      uint32_t &r3, uint32_t addr) {
    asm volatile("ldmatrix.sync.aligned.m8n8.x4.shared.b16 {%0,%1,%2,%3}, [%4];"
                 : "=r"(r0), "=r"(r1), "=r"(r2), "=r"(r3) : "r"(addr));
}
__device__ __forceinline__ void hmma(float (&d)[4], uint32_t a0, uint32_t a1,
                                     uint32_t a2, uint32_t a3, uint32_t b0, uint32_t b1) {
    asm volatile("mma.sync.aligned.m16n8k16.row.col.f32.f16.f16.f32 "
                 "{%0,%1,%2,%3}, {%4,%5,%6,%7}, {%8,%9}, {%0,%1,%2,%3};"
                 : "+f"(d[0]), "+f"(d[1]), "+f"(d[2]), "+f"(d[3])
                 : "r"(a0), "r"(a1), "r"(a2), "r"(a3), "r"(b0), "r"(b1));
}

// ---------------- sample-id (searchsorted right - 1) ------------------------
__global__ void sid_kernel(const int* __restrict__ starts, int* __restrict__ sid) {
    int i = blockIdx.x * 256 + threadIdx.x;
    if (i >= NROWS) return;
    int lo = 0, hi = BDIM - 1;
    while (lo < hi) {
        int mid = (lo + hi + 1) >> 1;
        if (starts[mid] <= i) lo = mid; else hi = mid - 1;
    }
    sid[i] = lo;
}

// ---------------- f32 -> f16 convert ----------------------------------------
__global__ __launch_bounds__(256)
void cvt_kernel(const float* __restrict__ src, __half* __restrict__ dst, int n4) {
    int i = blockIdx.x * 256 + threadIdx.x;
    if (i >= n4) return;
    float4 v = ((const float4*)src)[i];
    ((__half2*)dst)[2 * i]     = __floats2half2_rn(v.x, v.y);
    ((__half2*)dst)[2 * i + 1] = __floats2half2_rn(v.z, v.w);
}

// pack concat(neigh, dist) rows into f16 X[N, 320]
__global__ __launch_bounds__(256)
void cvtx_kernel(const float* __restrict__ neigh, const float* __restrict__ dist,
                 __half* __restrict__ xh) {
    int idx = blockIdx.x * 256 + threadIdx.x;          // N * 40 half8-chunks
    if (idx >= NROWS * 40) return;
    int row = idx / 40, c = idx % 40;
    const float* src = (c < 8) ? (neigh + (size_t)row * INF + c * 8)
                               : (dist + (size_t)row * DDIM + (c - 8) * 8);
    float4 v0 = ((const float4*)src)[0];
    float4 v1 = ((const float4*)src)[1];
    uint4 o;
    o.x = h2u(__floats2half2_rn(v0.x, v0.y));
    o.y = h2u(__floats2half2_rn(v0.z, v0.w));
    o.z = h2u(__floats2half2_rn(v1.x, v1.y));
    o.w = h2u(__floats2half2_rn(v1.z, v1.w));
    ((uint4*)(xh + (size_t)row * EK))[c] = o;
}

// W_embT[n][k'] = W_emb[sel(k')][n],  sel = k'<64 ? k' : k'+512  (f16, K-contig)
__global__ __launch_bounds__(256)
void wembT_kernel(const float* __restrict__ W, __half* __restrict__ wt) {
    int idx = blockIdx.x * 256 + threadIdx.x;          // 512 * 320
    if (idx >= HH * EK) return;
    int n = idx / EK, k = idx % EK;
    int kr = (k < INF) ? k : (k + 512);
    wt[idx] = __float2half(W[(size_t)kr * HH + n]);
}

// ---------------- FFMA2 GEMM: traj_emb = traj @ W_emb[64:576] (f32) ---------
#define TK  16
#define PADL 132

__global__ __launch_bounds__(256)
void traj_gemm_kernel(const float* __restrict__ A, const float* __restrict__ B,
                      float* __restrict__ C)
{
    __shared__ float As[2][TK][PADL];
    __shared__ float Bs[2][TK][PADL];

    const int tid = threadIdx.x;
    const int tx  = tid & 15, ty = tid >> 4;
    const int tx4 = tx * 4,  ty4 = ty * 4;
    const int m0 = blockIdx.y * 128;
    const int n0 = blockIdx.x * 128;

    int rowA[2], kvA[2], krB[2], jvB[2];
#pragma unroll
    for (int i = 0; i < 2; i++) {
        int l = i * 256 + tid;
        rowA[i] = l >> 2;  kvA[i] = (l & 3) * 4;
        krB[i]  = l >> 5;  jvB[i] = (l & 31) * 4;
    }

    unsigned long long acc[4][8];
#pragma unroll
    for (int i = 0; i < 4; i++)
#pragma unroll
        for (int j = 0; j < 8; j++) acc[i][j] = 0ull;

    auto fetchA = [&](int kt, float4* ra) {
#pragma unroll
        for (int i = 0; i < 2; i++)
            ra[i] = *(const float4*)(A + (size_t)(m0 + rowA[i]) * HH + kt * TK + kvA[i]);
    };
    auto fetchB = [&](int kt, float4* rb) {
#pragma unroll
        for (int i = 0; i < 2; i++)
            rb[i] = *(const float4*)(B + (size_t)(kt * TK + krB[i]) * HH + n0 + jvB[i]);
    };
    auto stA = [&](int nb, const float4* ra) {
#pragma unroll
        for (int i = 0; i < 2; i++) {
            As[nb][kvA[i] + 0][rowA[i]] = ra[i].x;
            As[nb][kvA[i] + 1][rowA[i]] = ra[i].y;
            As[nb][kvA[i] + 2][rowA[i]] = ra[i].z;
            As[nb][kvA[i] + 3][rowA[i]] = ra[i].w;
        }
    };
    auto stB = [&](int nb, const float4* rb) {
#pragma unroll
        for (int i = 0; i < 2; i++)
            *(float4*)&Bs[nb][krB[i]][jvB[i]] = rb[i];
    };

    {
        float4 ra[2], rb[2];
        fetchA(0, ra); fetchB(0, rb);
        stA(0, ra);    stB(0, rb);
    }
    __syncthreads();

    int buf = 0;
    const int tiles = HH / TK;
    for (int kt = 0; kt < tiles; kt++) {
        float4 ra[2], rb[2];
        const bool more = (kt + 1 < tiles);
        if (more) { fetchA(kt + 1, ra); fetchB(kt + 1, rb); }

#pragma unroll
        for (int k = 0; k < TK; k++) {
            ulonglong2 au0 = *(const ulonglong2*)&As[buf][k][ty4];
            ulonglong2 au1 = *(const ulonglong2*)&As[buf][k][64 + ty4];
            float4 bf0 = *(const float4*)&Bs[buf][k][tx4];
            float4 bf1 = *(const float4*)&Bs[buf][k][64 + tx4];
            unsigned long long a2[4] = {au0.x, au0.y, au1.x, au1.y};
            unsigned long long bb[8] = {dup2(bf0.x), dup2(bf0.y), dup2(bf0.z), dup2(bf0.w),
                                        dup2(bf1.x), dup2(bf1.y), dup2(bf1.z), dup2(bf1.w)};
#pragma unroll
            for (int mp = 0; mp < 4; mp++)
#pragma unroll
                for (int c = 0; c < 8; c++)
                    fma2(acc[mp][c], a2[mp], bb[c]);
        }

        if (more) { stA(buf ^ 1, ra); stB(buf ^ 1, rb); }
        __syncthreads();
        buf ^= 1;
    }

    float2 u[4][8];
#pragma unroll
    for (int mp = 0; mp < 4; mp++)
#pragma unroll
        for (int c = 0; c < 8; c++) u[mp][c] = unpk(acc[mp][c]);

#pragma unroll
    for (int g = 0; g < 2; g++)
#pragma unroll
        for (int pr = 0; pr < 2; pr++) {
            const int mp = g * 2 + pr;
#pragma unroll
            for (int lane = 0; lane < 2; lane++) {
                const int r = m0 + g * 64 + ty4 + pr * 2 + lane;
#pragma unroll
                for (int cg = 0; cg < 2; cg++) {
                    const int col = n0 + cg * 64 + tx4;
                    float4 v;
                    v.x = lane ? u[mp][cg * 4 + 0].y : u[mp][cg * 4 + 0].x;
                    v.y = lane ? u[mp][cg * 4 + 1].y : u[mp][cg * 4 + 1].x;
                    v.z = lane ? u[mp][cg * 4 + 2].y : u[mp][cg * 4 + 2].x;
                    v.w = lane ? u[mp][cg * 4 + 3].y : u[mp][cg * 4 + 3].x;
                    *(float4*)&C[(size_t)r * HH + col] = v;
                }
            }
        }
}

// ---------------- HMMA emb kernel -------------------------------------------
// CTA: 128 rows x 64 cols, 8 warps. K=320 in 5 chunks of 64. Stage 24KB:
// A 128x64 f16 (16KB) + B 64x64 f16 (8KB). Double-buffered (48KB).
#define ES_STAGE 24576u
#define ES_BIAS  49152u
#define ES_SMEM  49472u

__global__ __launch_bounds__(256, 1)
void emb_mma_kernel(const __half* __restrict__ xh, const __half* __restrict__ wt,
                    const float* __restrict__ traj_emb, const float* __restrict__ bias,
                    const int* __restrict__ sid, __half* __restrict__ emb)
{
    extern __shared__ char smem[];
    const uint32_t sb = smem_u32(smem);
    const int tid = threadIdx.x, wid = tid >> 5, lane = tid & 31;
    const int m0 = blockIdx.y * 128;
    const int j0 = blockIdx.x * 64;

    float* bp = (float*)(smem + ES_BIAS);
    if (tid < 64) bp[tid] = bias[j0 + tid];

    float acc[8][4];
#pragma unroll
    for (int n = 0; n < 8; n++)
#pragma unroll
        for (int e = 0; e < 4; e++) acc[n][e] = 0.f;

    uint4 pf[6];
    auto fetch = [&](int kc) {
#pragma unroll
        for (int i = 0; i < 6; i++) {
            int u = i * 256 + tid;                     // 0..1535
            const __half* src = (u < 1024)
                ? (xh + (size_t)(m0 + (u >> 3)) * EK + kc * 64 + (u & 7) * 8)
                : (wt + (size_t)(j0 + ((u - 1024) >> 3)) * EK + kc * 64 + ((u - 1024) & 7) * 8);
            pf[i] = *(const uint4*)src;
        }
    };
    auto store = [&](int buf) {
        const uint32_t bb = sb + (uint32_t)buf * ES_STAGE;
#pragma unroll
        for (int i = 0; i < 6; i++) {
            int u = i * 256 + tid;
            uint32_t off = (u < 1024)
                ? SWZ128((uint32_t)((u >> 3) * 128 + (u & 7) * 16))
                : (16384u + SWZ128((uint32_t)((((u - 1024) >> 3)) * 128 + ((u - 1024) & 7) * 16)));
            asm volatile("st.shared.v4.b32 [%0], {%1,%2,%3,%4};"
                         :: "r"(bb + off), "r"(pf[i].x), "r"(pf[i].y),
                            "r"(pf[i].z), "r"(pf[i].w));
        }
    };

    const uint32_t arow = (uint32_t)((wid << 4) + (lane & 15)) * 128u + ((lane >> 4) << 4);
    const int brow = (lane & 7) + ((lane >> 4) << 3);
    const uint32_t bkoff = (uint32_t)(((lane >> 3) & 1) << 4);

    fetch(0); store(0); __syncthreads();

    for (int kc = 0; kc < 5; kc++) {
        const int cur = kc & 1;
        if (kc < 4) fetch(kc + 1);

        const uint32_t base = sb + (uint32_t)cur * ES_STAGE;
#pragma unroll
        for (int ks = 0; ks < 4; ks++) {
            uint32_t a0, a1, a2, a3;
            ldsm4(a0, a1, a2, a3, base + SWZ128(arow + (uint32_t)ks * 32u));
#pragma unroll
            for (int nf2 = 0; nf2 < 4; nf2++) {
                uint32_t b0, b1, b2, b3;
                uint32_t ba = base + 16384u +
                    SWZ128((uint32_t)((nf2 * 16 + brow) * 128) + (uint32_t)ks * 32u + bkoff);
                ldsm4(b0, b1, b2, b3, ba);
                hmma(acc[nf2 * 2],     a0, a1, a2, a3, b0, b1);
                hmma(acc[nf2 * 2 + 1], a0, a1, a2, a3, b2, b3);
            }
        }

        if (kc < 4) { store(cur ^ 1); __syncthreads(); }
    }

    // ---------------- epilogue: + traj_emb[sid] + bias, relu, f16 store -----
    const int t4 = lane & 3, gid = lane >> 2;
    const int r0 = m0 + wid * 16 + gid;
    const int s0 = sid[r0], s1 = sid[r0 + 8];
    const float* tp0 = traj_emb + (size_t)s0 * HH + j0;
    const float* tp1 = traj_emb + (size_t)s1 * HH + j0;

#pragma unroll
    for (int nf = 0; nf < 8; nf++) {
        const int c = nf * 8 + 2 * t4;
        float2 t0 = *(const float2*)(tp0 + c);
        float2 t1 = *(const float2*)(tp1 + c);
        float b0 = bp[c], b1 = bp[c + 1];
        float e00 = fmaxf(acc[nf][0] + t0.x + b0, 0.f);
        float e01 = fmaxf(acc[nf][1] + t0.y + b1, 0.f);
        float e10 = fmaxf(acc[nf][2] + t1.x + b0, 0.f);
        float e11 = fmaxf(acc[nf][3] + t1.y + b1, 0.f);
        *(__half2*)(emb + (size_t)r0 * HH + j0 + c)       = __floats2half2_rn(e00, e01);
        *(__half2*)(emb + (size_t)(r0 + 8) * HH + j0 + c) = __floats2half2_rn(e10, e11);
    }
}

// ---------------- GRU gate math ---------------------------------------------
__device__ __forceinline__ float sigf(float x) { return 1.f / (1.f + __expf(-x)); }
__device__ __forceinline__ float tanhfast(float x) {
    float ax = fabsf(x);
    float e  = __expf(-2.f * ax);
    float t  = (1.f - e) / (1.f + e);
    return copysignf(t, x);
}
__device__ __forceinline__ float gru1(float sr, float sz, float i_n, float h_n, float h) {
    float r = sigf(sr);
    float z = sigf(sz);
    float n = tanhfast(i_n + r * h_n);
    return (1.f - z) * n + z * h;
}

// ---------------- fused HMMA kernel: gi/gh GEMMs + gates --------------------
#define FG_STAGE 40960u
#define FG_BIAS  81920u
#define FG_SMEM  83200u

template<int PHASE>
__device__ __forceinline__ void gemm_phase(
    uint32_t sb, const __half* __restrict__ Asrc, const __half* __restrict__ Bsrc,
    int m0, int j0, int tid, int wid, int lane, float (&acc)[4][8][4])
{
    uint4 pf[10];

    auto fetch = [&](int kc) {
#pragma unroll
        for (int i = 0; i < 10; i++) {
            int u = i * 256 + tid;
            const __half* src;
            if (u < 1024) {
                src = Asrc + (size_t)(m0 + (u >> 3)) * 512 + kc * 64 + (u & 7) * 8;
            } else {
                int v = u - 1024, g = v >> 9, w = v & 511;
                src = Bsrc + (size_t)(g * 512 + j0 + (w >> 3)) * 512 + kc * 64 + (w & 7) * 8;
            }
            pf[i] = *(const uint4*)src;
        }
    };
    auto store = [&](int buf) {
        const uint32_t bb = sb + (uint32_t)buf * FG_STAGE;
#pragma unroll
        for (int i = 0; i < 10; i++) {
            int u = i * 256 + tid;
            uint32_t off;
            if (u < 1024) {
                off = SWZ128((uint32_t)((u >> 3) * 128 + (u & 7) * 16));
            } else {
                int v = u - 1024, g = v >> 9, w = v & 511;
                off = 16384u + (uint32_t)g * 8192u +
                      SWZ128((uint32_t)((w >> 3) * 128 + (w & 7) * 16));
            }
            asm volatile("st.shared.v4.b32 [%0], {%1,%2,%3,%4};"
                         :: "r"(bb + off), "r"(pf[i].x), "r"(pf[i].y),
                            "r"(pf[i].z), "r"(pf[i].w));
        }
    };

    const uint32_t arow = (uint32_t)((wid << 4) + (lane & 15)) * 128u + ((lane >> 4) << 4);
    const int brow = (lane & 7) + ((lane >> 4) << 3);
    const uint32_t bkoff = (uint32_t)(((lane >> 3) & 1) << 4);

    fetch(0); store(0); __syncthreads();

    for (int kc = 0; kc < 8; kc++) {
        const int cur = kc & 1;
        if (kc < 7) fetch(kc + 1);

        const uint32_t base = sb + (uint32_t)cur * FG_STAGE;
#pragma unroll
        for (int ks = 0; ks < 4; ks++) {
            uint32_t a0, a1, a2, a3;
            ldsm4(a0, a1, a2, a3, base + SWZ128(arow + (uint32_t)ks * 32u));
#pragma unroll
            for (int g = 0; g < 3; g++) {
                const int grp = (g < 2) ? g : (2 + PHASE);
                const uint32_t boff = 16384u + (uint32_t)g * 8192u;
#pragma unroll
                for (int nf2 = 0; nf2 < 4; nf2++) {
                    uint32_t b0, b1, b2, b3;
                    uint32_t ba = base + boff +
                        SWZ128((uint32_t)((nf2 * 16 + brow) * 128) +
                               (uint32_t)ks * 32u + bkoff);
                    ldsm4(b0, b1, b2, b3, ba);
                    hmma(acc[grp][nf2 * 2],     a0, a1, a2, a3, b0, b1);
                    hmma(acc[grp][nf2 * 2 + 1], a0, a1, a2, a3, b2, b3);
                }
            }
        }

        if (kc < 7) { store(cur ^ 1); __syncthreads(); }
    }
}

__global__ __launch_bounds__(256, 1)
void fused_gru_kernel(const __half* __restrict__ emb_h, const __half* __restrict__ ht_h,
                      const __half* __restrict__ wih_h, const __half* __restrict__ whh_h,
                      const float* __restrict__ ht,
                      const float* __restrict__ b_ih, const float* __restrict__ b_hh,
                      float* __restrict__ out)
{
    extern __shared__ char smem[];
    const uint32_t sb = smem_u32(smem);
    const int tid = threadIdx.x, wid = tid >> 5, lane = tid & 31;
    const int m0 = blockIdx.y * 128;
    const int j0 = blockIdx.x * 64;

    float* bp = (float*)(smem + FG_BIAS);
    if (tid < 64) {
        int j = j0 + tid;
        bp[tid]       = b_ih[j]        + b_hh[j];
        bp[64 + tid]  = b_ih[512 + j]  + b_hh[512 + j];
        bp[128 + tid] = b_ih[1024 + j];
        bp[192 + tid] = b_hh[1024 + j];
    }

    float acc[4][8][4];
#pragma unroll
    for (int g = 0; g < 4; g++)
#pragma unroll
        for (int n = 0; n < 8; n++)
#pragma unroll
            for (int e = 0; e < 4; e++) acc[g][n][e] = 0.f;

    gemm_phase<0>(sb, emb_h, wih_h, m0, j0, tid, wid, lane, acc);
    __syncthreads();
    gemm_phase<1>(sb, ht_h, whh_h, m0, j0, tid, wid, lane, acc);

    const int t4 = lane & 3, gid = lane >> 2;
    const int r0 = m0 + wid * 16 + gid;

#pragma unroll
    for (int nf = 0; nf < 8; nf++) {
        const int c = nf * 8 + 2 * t4;
        const float* hp0 = ht + (size_t)r0 * HH + j0 + c;
        const float* hp1 = hp0 + 8 * HH;
        float2 h0 = *(const float2*)hp0;
        float2 h1 = *(const float2*)hp1;

        float2 o0, o1;
        o0.x = gru1(acc[0][nf][0] + bp[c],     acc[1][nf][0] + bp[64 + c],
                    acc[2][nf][0] + bp[128 + c], acc[3][nf][0] + bp[192 + c], h0.x);
        o0.y = gru1(acc[0][nf][1] + bp[c + 1], acc[1][nf][1] + bp[64 + c + 1],
                    acc[2][nf][1] + bp[128 + c + 1], acc[3][nf][1] + bp[192 + c + 1], h0.y);
        o1.x = gru1(acc[0][nf][2] + bp[c],     acc[1][nf][2] + bp[64 + c],
                    acc[2][nf][2] + bp[128 + c], acc[3][nf][2] + bp[192 + c], h1.x);
        o1.y = gru1(acc[0][nf][3] + bp[c + 1], acc[1][nf][3] + bp[64 + c + 1],
                    acc[2][nf][3] + bp[128 + c + 1], acc[3][nf][3] + bp[192 + c + 1], h1.y);

        *(float2*)(out + (size_t)r0 * HH + j0 + c)       = o0;
        *(float2*)(out + (size_t)(r0 + 8) * HH + j0 + c) = o1;
    }
}

// ---------------- launch ----------------------------------------------------
extern "C" void kernel_launch(void* const* d_in, const int* in_sizes, int n_in,
                              void* d_out, int out_size)
{
    const float* traj  = (const float*)d_in[0];
    const float* neigh = (const float*)d_in[1];
    const float* dist  = (const float*)d_in[2];
    const float* ht    = (const float*)d_in[3];
    const float* W_emb = (const float*)d_in[4];
    const float* b_emb = (const float*)d_in[5];
    const float* w_ih  = (const float*)d_in[6];
    const float* w_hh  = (const float*)d_in[7];
    const float* b_ih  = (const float*)d_in[8];
    const float* b_hh  = (const float*)d_in[9];
    const int*   starts = (const int*)d_in[10];
    float* out = (float*)d_out;

    float *p_traj_emb;
    __half *p_x_h, *p_wembT_h, *p_emb_h, *p_ht_h, *p_wih_h, *p_whh_h;
    int* p_sid;
    cudaGetSymbolAddress((void**)&p_traj_emb, g_traj_emb);
    cudaGetSymbolAddress((void**)&p_x_h, g_x_h);
    cudaGetSymbolAddress((void**)&p_wembT_h, g_wembT_h);
    cudaGetSymbolAddress((void**)&p_emb_h, g_emb_h);
    cudaGetSymbolAddress((void**)&p_ht_h, g_ht_h);
    cudaGetSymbolAddress((void**)&p_wih_h, g_wih_h);
    cudaGetSymbolAddress((void**)&p_whh_h, g_whh_h);
    cudaGetSymbolAddress((void**)&p_sid, g_sid);

    cudaFuncSetAttribute(fused_gru_kernel,
                         cudaFuncAttributeMaxDynamicSharedMemorySize, FG_SMEM);
    cudaFuncSetAttribute(emb_mma_kernel,
                         cudaFuncAttributeMaxDynamicSharedMemorySize, ES_SMEM);

    // 1) independents: sid, f16 packs/conversions
    sid_kernel<<<NROWS / 256, 256>>>(starts, p_sid);
    cvtx_kernel<<<(NROWS * 40) / 256, 256>>>(neigh, dist, p_x_h);
    wembT_kernel<<<(HH * EK) / 256, 256>>>(W_emb, p_wembT_h);
    cvt_kernel<<<(NROWS * HH / 4) / 256, 256>>>(ht, p_ht_h, NROWS * HH / 4);
    cvt_kernel<<<(3 * HH * HH / 4 + 255) / 256, 256>>>(w_ih, p_wih_h, 3 * HH * HH / 4);
    cvt_kernel<<<(3 * HH * HH / 4 + 255) / 256, 256>>>(w_hh, p_whh_h, 3 * HH * HH / 4);

    // 2) traj_emb = traj @ W_emb[64:576]  (exact f32, FFMA2)
    traj_gemm_kernel<<<dim3(HH / 128, BDIM / 128), 256>>>(
        traj, W_emb + (size_t)INF * HH, p_traj_emb);

    // 3) emb(f16) = relu(X @ WembT^T + traj_emb[sid] + b_emb)   [HMMA]
    emb_mma_kernel<<<dim3(HH / 64, NROWS / 128), 256, ES_SMEM>>>(
        p_x_h, p_wembT_h, p_traj_emb, b_emb, p_sid, p_emb_h);

    // 4) fused: gi/gh GEMMs (HMMA) + GRU gates -> out
    fused_gru_kernel<<<dim3(HH / 64, NROWS / 128), 256, FG_SMEM>>>(
        p_emb_h, p_ht_h, p_wih_h, p_whh_h, ht, b_ih, b_hh, out);
}